// round 1
// baseline (speedup 1.0000x reference)
#include <cuda_runtime.h>
#include <math_constants.h>

#define NB    1024          // batch rows
#define NF    1024          // features (x columns)
#define NK    (NF + 1)      // weight rows incl. bias row
#define NDIL  256
#define NERO  256
#define NOUT  (NDIL + NERO) // 512
#define RBLOCKS 256

// Scratch (no allocations allowed in kernel_launch)
__device__ float g_part[RBLOCKS * 4];   // per-block {dmax, dmin, emax, emin}
__device__ float g_spread[2];           // {Dmax-Dmin, Emax-Emin}

__device__ __forceinline__ float warp_max(float v) {
    #pragma unroll
    for (int o = 16; o > 0; o >>= 1) v = fmaxf(v, __shfl_xor_sync(0xffffffffu, v, o));
    return v;
}
__device__ __forceinline__ float warp_min(float v) {
    #pragma unroll
    for (int o = 16; o > 0; o >>= 1) v = fminf(v, __shfl_xor_sync(0xffffffffu, v, o));
    return v;
}

// ---------------------------------------------------------------------------
// Pass 1: per-block partial global max/min of both weight matrices.
// ---------------------------------------------------------------------------
__global__ __launch_bounds__(256) void spread_partial(
    const float* __restrict__ dil, const float* __restrict__ ero)
{
    const int tid = threadIdx.x;
    float dmax = -CUDART_INF_F, dmin = CUDART_INF_F;
    float emax = -CUDART_INF_F, emin = CUDART_INF_F;

    const int total = NK * NDIL;  // 262400 (same for erosions)
    for (int i = blockIdx.x * blockDim.x + tid; i < total; i += gridDim.x * blockDim.x) {
        float d = dil[i];
        dmax = fmaxf(dmax, d); dmin = fminf(dmin, d);
        float e = ero[i];
        emax = fmaxf(emax, e); emin = fminf(emin, e);
    }

    __shared__ float s[4][8];
    dmax = warp_max(dmax); dmin = warp_min(dmin);
    emax = warp_max(emax); emin = warp_min(emin);
    const int w = tid >> 5, l = tid & 31;
    if (l == 0) { s[0][w] = dmax; s[1][w] = dmin; s[2][w] = emax; s[3][w] = emin; }
    __syncthreads();
    if (w == 0) {
        dmax = (l < 8) ? s[0][l] : -CUDART_INF_F;  dmax = warp_max(dmax);
        dmin = (l < 8) ? s[1][l] :  CUDART_INF_F;  dmin = warp_min(dmin);
        emax = (l < 8) ? s[2][l] : -CUDART_INF_F;  emax = warp_max(emax);
        emin = (l < 8) ? s[3][l] :  CUDART_INF_F;  emin = warp_min(emin);
        if (l == 0) {
            g_part[blockIdx.x * 4 + 0] = dmax;
            g_part[blockIdx.x * 4 + 1] = dmin;
            g_part[blockIdx.x * 4 + 2] = emax;
            g_part[blockIdx.x * 4 + 3] = emin;
        }
    }
}

// ---------------------------------------------------------------------------
// Pass 2: reduce the 256 partials -> spreads.
// ---------------------------------------------------------------------------
__global__ __launch_bounds__(256) void spread_final()
{
    const int tid = threadIdx.x;
    float dmax = g_part[tid * 4 + 0];
    float dmin = g_part[tid * 4 + 1];
    float emax = g_part[tid * 4 + 2];
    float emin = g_part[tid * 4 + 3];

    __shared__ float s[4][8];
    dmax = warp_max(dmax); dmin = warp_min(dmin);
    emax = warp_max(emax); emin = warp_min(emin);
    const int w = tid >> 5, l = tid & 31;
    if (l == 0) { s[0][w] = dmax; s[1][w] = dmin; s[2][w] = emax; s[3][w] = emin; }
    __syncthreads();
    if (w == 0) {
        dmax = (l < 8) ? s[0][l] : -CUDART_INF_F;  dmax = warp_max(dmax);
        dmin = (l < 8) ? s[1][l] :  CUDART_INF_F;  dmin = warp_min(dmin);
        emax = (l < 8) ? s[2][l] : -CUDART_INF_F;  emax = warp_max(emax);
        emin = (l < 8) ? s[3][l] :  CUDART_INF_F;  emin = warp_min(emin);
        if (l == 0) {
            g_spread[0] = dmax - dmin;   // >= 0
            g_spread[1] = emax - emin;   // >= 0
        }
    }
}

// ---------------------------------------------------------------------------
// Pass 3: one block per batch row. Exact candidate pruning:
//   argmax_k (x[k]+d[k,j]) must satisfy x[k] >= xmax - (Dmax-Dmin)
//   argmin_k (x[k]-e[k,j]) must satisfy x[k] <= xmin + (Emax-Emin)
// Candidate lists have full worst-case capacity (NK), so correctness never
// depends on the pruning being effective.
// ---------------------------------------------------------------------------
__global__ __launch_bounds__(256) void dilate_erode_main(
    const float* __restrict__ x,
    const float* __restrict__ dil,
    const float* __restrict__ ero,
    float* __restrict__ out)
{
    __shared__ float sx[NK];
    __shared__ int   candD[NK];
    __shared__ int   candE[NK];
    __shared__ int   ncD, ncE;
    __shared__ float s_red[4][8];
    __shared__ float s_xmax, s_xmin;

    const int tid = threadIdx.x;
    const int b   = blockIdx.x;

    if (tid == 0) { ncD = 0; ncE = 0; }

    // Load row (incl. implicit bias 0 at k = NF) + local max/min.
    float vmax = -CUDART_INF_F, vmin = CUDART_INF_F;
    for (int k = tid; k < NK; k += 256) {
        float v = (k < NF) ? x[b * NF + k] : 0.0f;
        sx[k] = v;
        vmax = fmaxf(vmax, v);
        vmin = fminf(vmin, v);
    }

    // Block reduce max/min.
    vmax = warp_max(vmax); vmin = warp_min(vmin);
    const int w = tid >> 5, l = tid & 31;
    if (l == 0) { s_red[0][w] = vmax; s_red[1][w] = vmin; }
    __syncthreads();
    if (w == 0) {
        vmax = (l < 8) ? s_red[0][l] : -CUDART_INF_F;  vmax = warp_max(vmax);
        vmin = (l < 8) ? s_red[1][l] :  CUDART_INF_F;  vmin = warp_min(vmin);
        if (l == 0) { s_xmax = vmax; s_xmin = vmin; }
    }
    __syncthreads();

    // Candidate scan (inclusive thresholds -> exact).
    const float thD = s_xmax - g_spread[0];
    const float thE = s_xmin + g_spread[1];
    for (int k = tid; k < NK; k += 256) {
        float v = sx[k];
        if (v >= thD) { int p = atomicAdd(&ncD, 1); candD[p] = k; }
        if (v <= thE) { int p = atomicAdd(&ncE, 1); candE[p] = k; }
    }
    __syncthreads();

    const int nD = ncD, nE = ncE;

    // Each thread owns one output column j = tid for both halves.
    float dv = -CUDART_INF_F;
    for (int c = 0; c < nD; c++) {
        int k = candD[c];
        dv = fmaxf(dv, sx[k] + dil[k * NDIL + tid]);
    }
    float ev = CUDART_INF_F;
    for (int c = 0; c < nE; c++) {
        int k = candE[c];
        ev = fminf(ev, sx[k] - ero[k * NERO + tid]);
    }

    out[b * NOUT + tid]        = ev;   // eroded  -> cols [0, 256)
    out[b * NOUT + NERO + tid] = dv;   // dilated -> cols [256, 512)
}

extern "C" void kernel_launch(void* const* d_in, const int* in_sizes, int n_in,
                              void* d_out, int out_size)
{
    (void)in_sizes; (void)n_in; (void)out_size;
    const float* x   = (const float*)d_in[0];
    const float* dil = (const float*)d_in[1];
    const float* ero = (const float*)d_in[2];
    float* out = (float*)d_out;

    spread_partial<<<RBLOCKS, 256>>>(dil, ero);
    spread_final<<<1, 256>>>();
    dilate_erode_main<<<NB, 256>>>(x, dil, ero, out);
}

// round 2
// speedup vs baseline: 1.0824x; 1.0824x over previous
#include <cuda_runtime.h>
#include <math_constants.h>

#define NB    1024          // batch rows
#define NF    1024          // features
#define NK    (NF + 1)      // weight rows incl. bias row
#define NDIL  256
#define NERO  256
#define NOUT  (NDIL + NERO) // 512
#define CAP   256           // candidate list capacity (overflow -> exact fallback)

// g_bounds: all maintained as atomicMax over order-preserving uint encodings.
//   [0] = enc(max dil)   [1] = ~enc(min dil)   [2] = enc(max ero)   [3] = ~enc(min ero)
// All initialized to 0 via a single cudaMemsetAsync (0 = smallest encoded key).
__device__ unsigned g_bounds[4];

// Order-preserving float<->uint encoding: enc monotone increasing.
__device__ __forceinline__ unsigned enc_f(float f) {
    unsigned u = __float_as_uint(f);
    return (u & 0x80000000u) ? ~u : (u | 0x80000000u);
}
__device__ __forceinline__ float dec_f(unsigned u) {
    return (u & 0x80000000u) ? __uint_as_float(u & 0x7fffffffu)
                             : __uint_as_float(~u);
}

__device__ __forceinline__ float warp_max(float v) {
    #pragma unroll
    for (int o = 16; o > 0; o >>= 1) v = fmaxf(v, __shfl_xor_sync(0xffffffffu, v, o));
    return v;
}
__device__ __forceinline__ float warp_min(float v) {
    #pragma unroll
    for (int o = 16; o > 0; o >>= 1) v = fminf(v, __shfl_xor_sync(0xffffffffu, v, o));
    return v;
}

// ---------------------------------------------------------------------------
// Pass 1 (single kernel): global max/min of both weight matrices via float4
// loads + block reduce + 4 global atomicMax on encoded keys.
// NK*NDIL = 262400 floats = 65600 float4 per matrix.
// ---------------------------------------------------------------------------
__global__ __launch_bounds__(256) void spread_kernel(
    const float4* __restrict__ dil4, const float4* __restrict__ ero4)
{
    const int tid = threadIdx.x;
    const int i   = blockIdx.x * 256 + tid;      // 0..65535
    const int TOTAL4 = (NK * NDIL) / 4;          // 65600

    float dmax = -CUDART_INF_F, dmin = CUDART_INF_F;
    float emax = -CUDART_INF_F, emin = CUDART_INF_F;

    float4 d = dil4[i];
    float4 e = ero4[i];
    dmax = fmaxf(fmaxf(d.x, d.y), fmaxf(d.z, d.w));
    dmin = fminf(fminf(d.x, d.y), fminf(d.z, d.w));
    emax = fmaxf(fmaxf(e.x, e.y), fmaxf(e.z, e.w));
    emin = fminf(fminf(e.x, e.y), fminf(e.z, e.w));

    if (i < TOTAL4 - 65536) {                    // tail: 64 extra float4s
        float4 d2 = dil4[i + 65536];
        float4 e2 = ero4[i + 65536];
        dmax = fmaxf(dmax, fmaxf(fmaxf(d2.x, d2.y), fmaxf(d2.z, d2.w)));
        dmin = fminf(dmin, fminf(fminf(d2.x, d2.y), fminf(d2.z, d2.w)));
        emax = fmaxf(emax, fmaxf(fmaxf(e2.x, e2.y), fmaxf(e2.z, e2.w)));
        emin = fminf(emin, fminf(fminf(e2.x, e2.y), fminf(e2.z, e2.w)));
    }

    __shared__ float s[4][8];
    dmax = warp_max(dmax); dmin = warp_min(dmin);
    emax = warp_max(emax); emin = warp_min(emin);
    const int w = tid >> 5, l = tid & 31;
    if (l == 0) { s[0][w] = dmax; s[1][w] = dmin; s[2][w] = emax; s[3][w] = emin; }
    __syncthreads();
    if (w == 0) {
        dmax = (l < 8) ? s[0][l] : -CUDART_INF_F;  dmax = warp_max(dmax);
        dmin = (l < 8) ? s[1][l] :  CUDART_INF_F;  dmin = warp_min(dmin);
        emax = (l < 8) ? s[2][l] : -CUDART_INF_F;  emax = warp_max(emax);
        emin = (l < 8) ? s[3][l] :  CUDART_INF_F;  emin = warp_min(emin);
        if (l == 0) {
            atomicMax(&g_bounds[0],  enc_f(dmax));
            atomicMax(&g_bounds[1], ~enc_f(dmin));
            atomicMax(&g_bounds[2],  enc_f(emax));
            atomicMax(&g_bounds[3], ~enc_f(emin));
        }
    }
}

// ---------------------------------------------------------------------------
// Pass 2: one block per batch row. Exact candidate pruning:
//   argmax_k (x[k]+d[k,j])  requires  x[k] >= xmax - (Dmax-Dmin)
//   argmin_k (x[k]-e[k,j])  requires  x[k] <= xmin + (Emax-Emin)
// Candidate lists cap at CAP; on overflow fall back to exact brute force.
// ---------------------------------------------------------------------------
__global__ __launch_bounds__(256) void dilate_erode_main(
    const float* __restrict__ x,
    const float* __restrict__ dil,
    const float* __restrict__ ero,
    float* __restrict__ out)
{
    __shared__ float s_red[2][8];
    __shared__ float s_xmax, s_xmin;
    __shared__ int   candD[CAP], candE[CAP];
    __shared__ float cvD[CAP],  cvE[CAP];
    __shared__ int   ncD, ncE;

    const int tid = threadIdx.x;
    const int b   = blockIdx.x;

    if (tid == 0) { ncD = 0; ncE = 0; }

    // Spreads (4 broadcast LDGs, decoded per-thread — cheap).
    const float spreadD = dec_f(g_bounds[0]) - dec_f(~g_bounds[1]);
    const float spreadE = dec_f(g_bounds[2]) - dec_f(~g_bounds[3]);

    // Load this row's 4 features per thread (vectorized). Bias value 0 is
    // folded into the reduce inits (vmax=0, vmin=0).
    const float4 xr = reinterpret_cast<const float4*>(x + (size_t)b * NF)[tid];
    float vmax = fmaxf(0.0f, fmaxf(fmaxf(xr.x, xr.y), fmaxf(xr.z, xr.w)));
    float vmin = fminf(0.0f, fminf(fminf(xr.x, xr.y), fminf(xr.z, xr.w)));

    vmax = warp_max(vmax); vmin = warp_min(vmin);
    const int w = tid >> 5, l = tid & 31;
    if (l == 0) { s_red[0][w] = vmax; s_red[1][w] = vmin; }
    __syncthreads();
    if (w == 0) {
        vmax = (l < 8) ? s_red[0][l] : -CUDART_INF_F;  vmax = warp_max(vmax);
        vmin = (l < 8) ? s_red[1][l] :  CUDART_INF_F;  vmin = warp_min(vmin);
        if (l == 0) { s_xmax = vmax; s_xmin = vmin; }
    }
    __syncthreads();

    const float thD = s_xmax - spreadD;   // inclusive -> exact
    const float thE = s_xmin + spreadE;

    // Candidate scan over this thread's 4 features (+ bias at thread 0).
    {
        float v[4] = {xr.x, xr.y, xr.z, xr.w};
        #pragma unroll
        for (int q = 0; q < 4; q++) {
            int k = tid * 4 + q;
            if (v[q] >= thD) { int p = atomicAdd(&ncD, 1); if (p < CAP) { candD[p] = k; cvD[p] = v[q]; } }
            if (v[q] <= thE) { int p = atomicAdd(&ncE, 1); if (p < CAP) { candE[p] = k; cvE[p] = v[q]; } }
        }
        if (tid == 0) {   // bias feature k = NF, value 0
            if (0.0f >= thD) { int p = atomicAdd(&ncD, 1); if (p < CAP) { candD[p] = NF; cvD[p] = 0.0f; } }
            if (0.0f <= thE) { int p = atomicAdd(&ncE, 1); if (p < CAP) { candE[p] = NF; cvE[p] = 0.0f; } }
        }
    }
    __syncthreads();

    const int nD = ncD, nE = ncE;

    // Each thread owns output column j = tid for both halves.
    float dv = -CUDART_INF_F;
    if (nD <= CAP) {
        for (int c = 0; c < nD; c++)
            dv = fmaxf(dv, cvD[c] + dil[candD[c] * NDIL + tid]);
    } else {            // exact fallback (never expected, keeps worst case correct)
        for (int k = 0; k < NK; k++) {
            float xv = (k < NF) ? x[(size_t)b * NF + k] : 0.0f;
            dv = fmaxf(dv, xv + dil[k * NDIL + tid]);
        }
    }

    float ev = CUDART_INF_F;
    if (nE <= CAP) {
        for (int c = 0; c < nE; c++)
            ev = fminf(ev, cvE[c] - ero[candE[c] * NERO + tid]);
    } else {
        for (int k = 0; k < NK; k++) {
            float xv = (k < NF) ? x[(size_t)b * NF + k] : 0.0f;
            ev = fminf(ev, xv - ero[k * NERO + tid]);
        }
    }

    out[(size_t)b * NOUT + tid]        = ev;   // eroded  -> cols [0, 256)
    out[(size_t)b * NOUT + NERO + tid] = dv;   // dilated -> cols [256, 512)
}

extern "C" void kernel_launch(void* const* d_in, const int* in_sizes, int n_in,
                              void* d_out, int out_size)
{
    (void)in_sizes; (void)n_in; (void)out_size;
    const float* x   = (const float*)d_in[0];
    const float* dil = (const float*)d_in[1];
    const float* ero = (const float*)d_in[2];
    float* out = (float*)d_out;

    void* bounds_ptr = nullptr;
    cudaGetSymbolAddress(&bounds_ptr, g_bounds);
    cudaMemsetAsync(bounds_ptr, 0, 4 * sizeof(unsigned), 0);

    spread_kernel<<<256, 256>>>((const float4*)dil, (const float4*)ero);
    dilate_erode_main<<<NB, 256>>>(x, dil, ero, out);
}